// round 1
// baseline (speedup 1.0000x reference)
#include <cuda_runtime.h>

// ReLU_Conv (CROWN-style ReLU relaxation over bound maps)
// Shapes: lx/ux (C,H,W,hi,wi) = (32,32,32,32,32); lc/uc (32,32,32);
//         x_min/x_max (32,32).
// Per neuron n = (c,h,w): reduce 1024 inner elems -> l,u; then mask the row.
//
// Output buffer layout (concatenated, matching reference return order):
//   [0,                NEL)        lx_out
//   [NEL,            2*NEL)        ux_out
//   [2*NEL,          2*NEL+NN)     lc_out
//   [2*NEL+NN,       2*NEL+2*NN)   uc_out

__global__ __launch_bounds__(256, 8)
void relu_conv_kernel(
    const float* __restrict__ lx, const float* __restrict__ ux,
    const float* __restrict__ lc, const float* __restrict__ uc,
    const float* __restrict__ xmin, const float* __restrict__ xmax,
    float* __restrict__ lx_out, float* __restrict__ ux_out,
    float* __restrict__ lc_out, float* __restrict__ uc_out,
    int inner /* = 1024 */)
{
    const int n   = blockIdx.x;
    const int tid = threadIdx.x;                  // 0..255, one float4 each
    const size_t base = (size_t)n * (size_t)inner;

    // Vectorized, fully coalesced loads. Rows are inner*4 = 4096B aligned.
    const float4 vlx = reinterpret_cast<const float4*>(lx + base)[tid];
    const float4 vux = reinterpret_cast<const float4*>(ux + base)[tid];
    const float4 vmn = reinterpret_cast<const float4*>(xmin)[tid];
    const float4 vmx = reinterpret_cast<const float4*>(xmax)[tid];

    // mask_lower = lx>0 ? min : (lx<0 ? max : 0); suml += mask*lx
    // mask_upper = ux>0 ? max : (ux<0 ? min : 0); sumu += mask*ux
    float suml, sumu;
    {
        float a, b;
        a  = (vlx.x > 0.f ? vmn.x : (vlx.x < 0.f ? vmx.x : 0.f)) * vlx.x;
        b  = (vux.x > 0.f ? vmx.x : (vux.x < 0.f ? vmn.x : 0.f)) * vux.x;
        a += (vlx.y > 0.f ? vmn.y : (vlx.y < 0.f ? vmx.y : 0.f)) * vlx.y;
        b += (vux.y > 0.f ? vmx.y : (vux.y < 0.f ? vmn.y : 0.f)) * vux.y;
        a += (vlx.z > 0.f ? vmn.z : (vlx.z < 0.f ? vmx.z : 0.f)) * vlx.z;
        b += (vux.z > 0.f ? vmx.z : (vux.z < 0.f ? vmn.z : 0.f)) * vux.z;
        a += (vlx.w > 0.f ? vmn.w : (vlx.w < 0.f ? vmx.w : 0.f)) * vlx.w;
        b += (vux.w > 0.f ? vmx.w : (vux.w < 0.f ? vmn.w : 0.f)) * vux.w;
        suml = a; sumu = b;
    }

    // Warp reduction (two values per lane).
    #pragma unroll
    for (int off = 16; off; off >>= 1) {
        suml += __shfl_down_sync(0xffffffffu, suml, off);
        sumu += __shfl_down_sync(0xffffffffu, sumu, off);
    }

    __shared__ float sL[8], sU[8];
    __shared__ float s_alive, s_cross, s_slope;
    const int warp = tid >> 5, lane = tid & 31;
    if (lane == 0) { sL[warp] = suml; sU[warp] = sumu; }
    __syncthreads();

    if (tid == 0) {
        float l = 0.f, u = 0.f;
        #pragma unroll
        for (int i = 0; i < 8; i++) { l += sL[i]; u += sU[i]; }
        const float lcv = lc[n], ucv = uc[n];
        l += lcv; u += ucv;

        const bool alive = (l >= 0.f);
        const bool cross = (l < 0.f) && (u > 0.f);
        const float denom = cross ? (u - l) : 1.f;
        float slope = cross ? (u / denom) : 1.f;
        slope = fminf(fmaxf(slope, 0.f), 1.f);

        lc_out[n] = alive ? lcv : 0.f;
        uc_out[n] = alive ? ucv : (cross ? (slope * ucv - slope * l) : 0.f);

        s_alive = alive ? 1.f : 0.f;
        s_cross = cross ? 1.f : 0.f;
        s_slope = slope;
    }
    __syncthreads();

    const bool  alive = (s_alive != 0.f);
    const bool  cross = (s_cross != 0.f);
    const float slope = s_slope;

    float4 olx, oux;
    olx.x = alive ? vlx.x : 0.f;
    olx.y = alive ? vlx.y : 0.f;
    olx.z = alive ? vlx.z : 0.f;
    olx.w = alive ? vlx.w : 0.f;
    oux.x = alive ? vux.x : (cross ? slope * vux.x : 0.f);
    oux.y = alive ? vux.y : (cross ? slope * vux.y : 0.f);
    oux.z = alive ? vux.z : (cross ? slope * vux.z : 0.f);
    oux.w = alive ? vux.w : (cross ? slope * vux.w : 0.f);

    reinterpret_cast<float4*>(lx_out + base)[tid] = olx;
    reinterpret_cast<float4*>(ux_out + base)[tid] = oux;
}

extern "C" void kernel_launch(void* const* d_in, const int* in_sizes, int n_in,
                              void* d_out, int out_size)
{
    const float* lx   = (const float*)d_in[0];
    const float* ux   = (const float*)d_in[1];
    const float* lc   = (const float*)d_in[2];
    const float* uc   = (const float*)d_in[3];
    const float* xmin = (const float*)d_in[4];
    const float* xmax = (const float*)d_in[5];

    const int neurons = in_sizes[2];          // C*H*W = 32768
    const int inner   = in_sizes[4];          // hi*wi = 1024
    const size_t nel  = (size_t)neurons * (size_t)inner;

    float* out    = (float*)d_out;
    float* lx_out = out;
    float* ux_out = out + nel;
    float* lc_out = out + 2 * nel;
    float* uc_out = out + 2 * nel + neurons;

    const int threads = inner / 4;            // 256
    relu_conv_kernel<<<neurons, threads>>>(lx, ux, lc, uc, xmin, xmax,
                                           lx_out, ux_out, lc_out, uc_out,
                                           inner);
}

// round 2
// speedup vs baseline: 1.0604x; 1.0604x over previous
#include <cuda_runtime.h>

// ReLU_Conv (CROWN-style ReLU relaxation over bound maps)
// Shapes: lx/ux (C,H,W,hi,wi) = (32,32,32,32,32); lc/uc (32,32,32);
//         x_min/x_max (32,32).
// Round 2: 2 neurons per block (MLP=4 front-batched LDG.128/thread),
//          streaming cache hints (__ldcs/__stcs), single barrier with
//          redundant per-thread finalization.
//
// Output layout: [lx_out | ux_out | lc_out | uc_out]

__device__ __forceinline__ void acc_pair(const float4 l, const float4 u,
                                         const float4 mn, const float4 mx,
                                         float& sl, float& su)
{
    sl  = (l.x > 0.f ? mn.x : (l.x < 0.f ? mx.x : 0.f)) * l.x;
    su  = (u.x > 0.f ? mx.x : (u.x < 0.f ? mn.x : 0.f)) * u.x;
    sl += (l.y > 0.f ? mn.y : (l.y < 0.f ? mx.y : 0.f)) * l.y;
    su += (u.y > 0.f ? mx.y : (u.y < 0.f ? mn.y : 0.f)) * u.y;
    sl += (l.z > 0.f ? mn.z : (l.z < 0.f ? mx.z : 0.f)) * l.z;
    su += (u.z > 0.f ? mx.z : (u.z < 0.f ? mn.z : 0.f)) * u.z;
    sl += (l.w > 0.f ? mn.w : (l.w < 0.f ? mx.w : 0.f)) * l.w;
    su += (u.w > 0.f ? mx.w : (u.w < 0.f ? mn.w : 0.f)) * u.w;
}

__global__ __launch_bounds__(256, 5)
void relu_conv_kernel(
    const float* __restrict__ lx, const float* __restrict__ ux,
    const float* __restrict__ lc, const float* __restrict__ uc,
    const float* __restrict__ xmin, const float* __restrict__ xmax,
    float* __restrict__ lx_out, float* __restrict__ ux_out,
    float* __restrict__ lc_out, float* __restrict__ uc_out)
{
    const int tid = threadIdx.x;                       // 0..255
    const int n0  = blockIdx.x * 2;                    // neuron pair
    const int n1  = n0 + 1;
    const size_t base0 = (size_t)n0 * 1024;
    const size_t base1 = base0 + 1024;

    // Front-batched streaming loads (4x LDG.128 per thread, evict-first).
    const float4 vlx0 = __ldcs(reinterpret_cast<const float4*>(lx + base0) + tid);
    const float4 vux0 = __ldcs(reinterpret_cast<const float4*>(ux + base0) + tid);
    const float4 vlx1 = __ldcs(reinterpret_cast<const float4*>(lx + base1) + tid);
    const float4 vux1 = __ldcs(reinterpret_cast<const float4*>(ux + base1) + tid);
    // Broadcast bounds: heavily reused across all blocks -> normal caching.
    const float4 vmn = __ldg(reinterpret_cast<const float4*>(xmin) + tid);
    const float4 vmx = __ldg(reinterpret_cast<const float4*>(xmax) + tid);

    float sl0, su0, sl1, su1;
    acc_pair(vlx0, vux0, vmn, vmx, sl0, su0);
    acc_pair(vlx1, vux1, vmn, vmx, sl1, su1);

    // Warp reduction of 4 partials.
    #pragma unroll
    for (int off = 16; off; off >>= 1) {
        sl0 += __shfl_down_sync(0xffffffffu, sl0, off);
        su0 += __shfl_down_sync(0xffffffffu, su0, off);
        sl1 += __shfl_down_sync(0xffffffffu, sl1, off);
        su1 += __shfl_down_sync(0xffffffffu, su1, off);
    }

    __shared__ float4 sPart[8];                        // (sl0, su0, sl1, su1) per warp
    const int warp = tid >> 5, lane = tid & 31;
    if (lane == 0) sPart[warp] = make_float4(sl0, su0, sl1, su1);
    __syncthreads();                                   // the ONLY barrier

    // Every thread redundantly finalizes (broadcast smem reads, no 2nd barrier).
    float l0 = 0.f, u0 = 0.f, l1 = 0.f, u1 = 0.f;
    #pragma unroll
    for (int i = 0; i < 8; i++) {
        const float4 p = sPart[i];
        l0 += p.x; u0 += p.y; l1 += p.z; u1 += p.w;
    }
    const float lc0 = lc[n0], uc0 = uc[n0];
    const float lc1 = lc[n1], uc1 = uc[n1];
    l0 += lc0; u0 += uc0;
    l1 += lc1; u1 += uc1;

    const bool alive0 = (l0 >= 0.f);
    const bool cross0 = (l0 < 0.f) && (u0 > 0.f);
    float slope0 = cross0 ? (u0 / (u0 - l0)) : 1.f;
    slope0 = fminf(fmaxf(slope0, 0.f), 1.f);

    const bool alive1 = (l1 >= 0.f);
    const bool cross1 = (l1 < 0.f) && (u1 > 0.f);
    float slope1 = cross1 ? (u1 / (u1 - l1)) : 1.f;
    slope1 = fminf(fmaxf(slope1, 0.f), 1.f);

    if (tid == 0) {
        lc_out[n0] = alive0 ? lc0 : 0.f;
        uc_out[n0] = alive0 ? uc0 : (cross0 ? (slope0 * uc0 - slope0 * l0) : 0.f);
        lc_out[n1] = alive1 ? lc1 : 0.f;
        uc_out[n1] = alive1 ? uc1 : (cross1 ? (slope1 * uc1 - slope1 * l1) : 0.f);
    }

    float4 o;
    // lx_out neuron 0
    o.x = alive0 ? vlx0.x : 0.f;  o.y = alive0 ? vlx0.y : 0.f;
    o.z = alive0 ? vlx0.z : 0.f;  o.w = alive0 ? vlx0.w : 0.f;
    __stcs(reinterpret_cast<float4*>(lx_out + base0) + tid, o);
    // ux_out neuron 0
    o.x = alive0 ? vux0.x : (cross0 ? slope0 * vux0.x : 0.f);
    o.y = alive0 ? vux0.y : (cross0 ? slope0 * vux0.y : 0.f);
    o.z = alive0 ? vux0.z : (cross0 ? slope0 * vux0.z : 0.f);
    o.w = alive0 ? vux0.w : (cross0 ? slope0 * vux0.w : 0.f);
    __stcs(reinterpret_cast<float4*>(ux_out + base0) + tid, o);
    // lx_out neuron 1
    o.x = alive1 ? vlx1.x : 0.f;  o.y = alive1 ? vlx1.y : 0.f;
    o.z = alive1 ? vlx1.z : 0.f;  o.w = alive1 ? vlx1.w : 0.f;
    __stcs(reinterpret_cast<float4*>(lx_out + base1) + tid, o);
    // ux_out neuron 1
    o.x = alive1 ? vux1.x : (cross1 ? slope1 * vux1.x : 0.f);
    o.y = alive1 ? vux1.y : (cross1 ? slope1 * vux1.y : 0.f);
    o.z = alive1 ? vux1.z : (cross1 ? slope1 * vux1.z : 0.f);
    o.w = alive1 ? vux1.w : (cross1 ? slope1 * vux1.w : 0.f);
    __stcs(reinterpret_cast<float4*>(ux_out + base1) + tid, o);
}

extern "C" void kernel_launch(void* const* d_in, const int* in_sizes, int n_in,
                              void* d_out, int out_size)
{
    const float* lx   = (const float*)d_in[0];
    const float* ux   = (const float*)d_in[1];
    const float* lc   = (const float*)d_in[2];
    const float* uc   = (const float*)d_in[3];
    const float* xmin = (const float*)d_in[4];
    const float* xmax = (const float*)d_in[5];

    const int neurons = in_sizes[2];          // C*H*W = 32768
    const int inner   = 1024;                 // hi*wi
    const size_t nel  = (size_t)neurons * (size_t)inner;

    float* out    = (float*)d_out;
    float* lx_out = out;
    float* ux_out = out + nel;
    float* lc_out = out + 2 * nel;
    float* uc_out = out + 2 * nel + neurons;

    relu_conv_kernel<<<neurons / 2, 256>>>(lx, ux, lc, uc, xmin, xmax,
                                           lx_out, ux_out, lc_out, uc_out);
}